// round 10
// baseline (speedup 1.0000x reference)
#include <cuda_runtime.h>
#include <cuda_fp16.h>
#include <math.h>
#include <stdint.h>

#define NMAX 10000
#define EMAX 160000
#define KT   125
#define CI1  64
#define CC   128
#define LD1  (KT*CI1 + CI1)    // 8064
#define LD2  (KT*CC + CC)      // 16128

// ---------------- scratch (device globals: no allocations allowed) ----------
__device__ __align__(1024) __half g_acc[(size_t)NMAX * LD2];  // 322MB
__device__ __align__(1024) __half g_wt1[CC * LD1];            // conv1 weights [n][k]
__device__ __align__(1024) __half g_wt2[CC * LD2];            // conv2 weights [n][k]
__device__ __align__(1024) __half g_wts[CC * CC];             // shortcut weights [n][k]
__device__ __align__(1024) __half g_sin[NMAX * CC];           // [s_agg | x] shortcut A
__device__ __align__(1024) __half g_h1e[NMAX * CC];           // elu(bn1(conv1)) fp16
__device__ __align__(1024) float g_part[3 * (size_t)NMAX * CC]; // split-K partials
__device__ __align__(1024) float g_out1[NMAX * CC];
__device__ __align__(1024) float g_out2[NMAX * CC];
__device__ __align__(1024) float g_outs[NMAX * CC];
__device__ __align__(16) float g_w8  [EMAX * 8];   // CSR-ordered basis weights
__device__ __align__(16) int   g_idx8[EMAX * 8];   // CSR-ordered kernel indices
__device__ int   g_srco[EMAX];                     // CSR-ordered source node
__device__ int   g_rowptr[NMAX + 1];
__device__ int   g_cursor[NMAX];
__device__ int   g_degcnt[NMAX];
__device__ float g_red  [6 * CC];
__device__ float g_scale[3 * CC];
__device__ float g_shift[3 * CC];

// ---------------- helpers ----------------------------------------------------
__device__ __forceinline__ uint32_t smem_u32(const void* p) {
    uint32_t a;
    asm("{ .reg .u64 t; cvta.to.shared.u64 t, %1; cvt.u32.u64 %0, t; }" : "=r"(a) : "l"(p));
    return a;
}
__device__ __forceinline__ void cp_async16(uint32_t dst, const void* src, int vsize) {
    asm volatile("cp.async.cg.shared.global [%0], [%1], 16, %2;"
                 :: "r"(dst), "l"(src), "r"(vsize) : "memory");
}
#define CP_COMMIT() asm volatile("cp.async.commit_group;" ::: "memory")
#define CP_WAIT(n)  asm volatile("cp.async.wait_group %0;" :: "n"(n) : "memory")

__device__ __forceinline__ void ldsm4(uint32_t* r, uint32_t addr) {
    asm volatile("ldmatrix.sync.aligned.m8n8.x4.shared.b16 {%0,%1,%2,%3}, [%4];"
                 : "=r"(r[0]), "=r"(r[1]), "=r"(r[2]), "=r"(r[3]) : "r"(addr));
}
__device__ __forceinline__ void mma_f16(float* c, const uint32_t* a, uint32_t b0, uint32_t b1) {
    asm volatile("mma.sync.aligned.m16n8k16.row.col.f32.f16.f16.f32 "
                 "{%0,%1,%2,%3}, {%4,%5,%6,%7}, {%8,%9}, {%0,%1,%2,%3};"
                 : "+f"(c[0]), "+f"(c[1]), "+f"(c[2]), "+f"(c[3])
                 : "r"(a[0]), "r"(a[1]), "r"(a[2]), "r"(a[3]), "r"(b0), "r"(b1));
}

// ---------------- CSR build --------------------------------------------------
__global__ void k_pre(const int* __restrict__ dst, int E) {
    int e = blockIdx.x * blockDim.x + threadIdx.x;
    if (e < E) atomicAdd(&g_degcnt[dst[e]], 1);
}

__global__ void k_scan(int n) {
    __shared__ int sh[1024];
    __shared__ int carry;
    int t = threadIdx.x;
    if (t == 0) carry = 0;
    __syncthreads();
    for (int base = 0; base < n; base += 1024) {
        int i = base + t;
        int v = (i < n) ? g_degcnt[i] : 0;
        sh[t] = v;
        __syncthreads();
        for (int off = 1; off < 1024; off <<= 1) {
            int tv = (t >= off) ? sh[t - off] : 0;
            __syncthreads();
            sh[t] += tv;
            __syncthreads();
        }
        if (i < n) {
            int ex = carry + sh[t] - v;
            g_rowptr[i] = ex;
            g_cursor[i] = ex;
        }
        __syncthreads();
        if (t == 0) carry += sh[1023];
        __syncthreads();
    }
    if (t == 0) g_rowptr[n] = carry;
}

// CSR fill: slot by atomic cursor, spline basis computed and stored IN CSR ORDER
__global__ void k_fill(const float* __restrict__ attr, const int* __restrict__ src,
                       const int* __restrict__ dst, int E) {
    int e = blockIdx.x * blockDim.x + threadIdx.x;
    if (e >= E) return;
    int pos = atomicAdd(&g_cursor[dst[e]], 1);
    g_srco[pos] = src[e];
    float v0 = attr[e * 3 + 0] * 4.f, v1 = attr[e * 3 + 1] * 4.f, v2 = attr[e * 3 + 2] * 4.f;
    float b0 = floorf(v0), b1 = floorf(v1), b2 = floorf(v2);
    float f0 = v0 - b0, f1 = v1 - b1, f2 = v2 - b2;
    int i0 = (int)b0, i1 = (int)b1, i2 = (int)b2;
#pragma unroll
    for (int m = 0; m < 8; m++) {
        int t0 = m & 1, t1 = (m >> 1) & 1, t2 = (m >> 2) & 1;
        float w = (t0 ? f0 : 1.f - f0) * (t1 ? f1 : 1.f - f1) * (t2 ? f2 : 1.f - f2);
        int c0 = min(max(i0 + t0, 0), 4);
        int c1 = min(max(i1 + t1, 0), 4);
        int c2 = min(max(i2 + t2, 0), 4);
        g_idx8[pos * 8 + m] = (c0 * 5 + c1) * 5 + c2;
        g_w8[pos * 8 + m] = w;
    }
}

// ---------------- aggregation: linear CSR reads, pipelined x prefetch --------
template <int CI, int WITH_S, typename T>
__global__ void k_agg(const T* __restrict__ X, const float* __restrict__ Xroot, int ldacc) {
    extern __shared__ float acc[];
    int n = blockIdx.x;
    int c = threadIdx.x;
    float4 z4 = make_float4(0.f, 0.f, 0.f, 0.f);
    for (int i = c; i < KT * CI / 4; i += CI) ((float4*)acc)[i] = z4;
    int jb = g_rowptr[n], je = g_rowptr[n + 1];
    float invd = (je > jb) ? 1.f / (float)(je - jb) : 1.f;
    float ss = 0.f;
    __syncthreads();
    float xv = 0.f;
    if (jb < je) xv = (float)X[(size_t)g_srco[jb] * CI + c];
    for (int j = jb; j < je; j++) {
        float xc = xv;
        if (j + 1 < je) xv = (float)X[(size_t)g_srco[j + 1] * CI + c];   // prefetch
        if (WITH_S) ss += xc;
#pragma unroll
        for (int m = 0; m < 8; m++) {
            int ki = g_idx8[j * 8 + m];
            float w = g_w8[j * 8 + m];
            acc[ki * CI + c] += w * xc;
        }
    }
    __syncthreads();
    size_t base = (size_t)n * ldacc;
    __half2* hp = (__half2*)(g_acc + base);
    for (int i = c; i < KT * CI / 2; i += CI)
        hp[i] = __floats2half2_rn(acc[2 * i] * invd, acc[2 * i + 1] * invd);
    g_acc[base + KT * CI + c] = (__half)(float)X[(size_t)n * CI + c];
    if (WITH_S) {
        g_sin[n * CC + c]       = __float2half(ss * invd);
        g_sin[n * CC + CI1 + c] = __float2half(Xroot[n * CI1 + c]);
    }
}

// fused tiled transpose of all three weight sets -> wt[n][k] fp16
__global__ void k_transp3(const float* __restrict__ W1, const float* __restrict__ Wr1,
                          const float* __restrict__ W2, const float* __restrict__ Wr2,
                          const float* __restrict__ Ws, const float* __restrict__ Wrs,
                          __half* __restrict__ wt1, __half* __restrict__ wt2,
                          __half* __restrict__ wts) {
    __shared__ float tile[32][33];
    const float *W, *Wr; __half* out; int Kmain, Ktot;
    if (blockIdx.z == 0) { W = W1; Wr = Wr1; out = wt1; Kmain = KT * CI1; Ktot = LD1; }
    else if (blockIdx.z == 1) { W = W2; Wr = Wr2; out = wt2; Kmain = KT * CC; Ktot = LD2; }
    else { W = Ws; Wr = Wrs; out = wts; Kmain = CI1; Ktot = CC; }
    int kb = blockIdx.x * 32, nb = blockIdx.y * 32;
    if (kb >= Ktot) return;
    int tx = threadIdx.x, ty = threadIdx.y;
#pragma unroll
    for (int i = 0; i < 32; i += 8) {
        int k = kb + ty + i;
        const float* srcp = (k < Kmain) ? &W[(size_t)k * CC] : &Wr[(size_t)(k - Kmain) * CC];
        tile[ty + i][tx] = srcp[nb + tx];
    }
    __syncthreads();
#pragma unroll
    for (int i = 0; i < 32; i += 8) {
        int nn = nb + ty + i;
        out[(size_t)nn * Ktot + kb + tx] = __float2half(tile[tx][ty + i]);
    }
}

// ---------------- fp16 mma.sync GEMM with ldmatrix feed -----------------------
#define BK 64
#define NSTAGE 3
#define STG_BYTES 32768
#define TILE_BYTES 16384

__global__ __launch_bounds__(256, 2)
void k_mgemm(const __half* __restrict__ A, const __half* __restrict__ B, int ld,
             int M, float* __restrict__ P, int pstride, int chunks) {
    extern __shared__ char sm[];
    int tid = threadIdx.x, lane = tid & 31, wid = tid >> 5;
    int m0 = blockIdx.x * 128;
    int kb0 = blockIdx.y * chunks * BK;

    int pr_r = tid >> 1;
    int pr_h = (tid & 1) * 4;
    int grow = m0 + pr_r;
    int vA = (grow < M) ? 16 : 0;
    const __half* Abase = A + (size_t)grow * ld + kb0;
    const __half* Bbase = B + (size_t)pr_r * ld + kb0;

    const int warp_m0 = (wid & 3) * 32;
    const int warp_n0 = (wid >> 2) * 64;
    int g = lane >> 2, t = lane & 3;

    uint32_t aoff[2]; int arx[2];
#pragma unroll
    for (int mf = 0; mf < 2; mf++) {
        int r = warp_m0 + mf * 16 + (lane & 15);
        aoff[mf] = r * 128; arx[mf] = r & 7;
    }
    int acb = lane >> 4;
    int grp = lane >> 3;
    int nf_half = grp >> 1, bcb = grp & 1;
    uint32_t boff[4]; int brx[4];
#pragma unroll
    for (int nfp = 0; nfp < 4; nfp++) {
        int r = warp_n0 + (nfp * 2 + nf_half) * 8 + (lane & 7);
        boff[nfp] = r * 128; brx[nfp] = r & 7;
    }

    float c[2][8][4];
#pragma unroll
    for (int i = 0; i < 2; i++)
#pragma unroll
        for (int j = 0; j < 8; j++)
#pragma unroll
            for (int q = 0; q < 4; q++) c[i][j][q] = 0.f;

    uint32_t smb = smem_u32(sm);

#define ISSUE(IT) do { \
    int _it = (IT); \
    if (_it < chunks) { \
        int _s = _it % NSTAGE; \
        uint32_t _dA = smb + _s * STG_BYTES + pr_r * 128; \
        uint32_t _dB = _dA + TILE_BYTES; \
        const __half* _sa = Abase + _it * BK; \
        const __half* _sb = Bbase + _it * BK; \
        _Pragma("unroll") \
        for (int _j = 0; _j < 4; _j++) { \
            int _c = pr_h + _j; \
            int _sc = _c ^ (pr_r & 7); \
            cp_async16(_dA + _sc * 16, _sa + _c * 8, vA); \
            cp_async16(_dB + _sc * 16, _sb + _c * 8, 16); \
        } \
    } \
    CP_COMMIT(); \
} while (0)

    ISSUE(0); ISSUE(1);

    for (int it = 0; it < chunks; it++) {
        CP_WAIT(1);
        __syncthreads();
        ISSUE(it + 2);
        uint32_t sA = smb + (it % NSTAGE) * STG_BYTES;
        uint32_t sB = sA + TILE_BYTES;
#pragma unroll
        for (int ks = 0; ks < 4; ks++) {
            int ca = ks * 2 + acb;
            uint32_t a[2][4];
            ldsm4(a[0], sA + aoff[0] + ((ca ^ arx[0]) << 4));
            ldsm4(a[1], sA + aoff[1] + ((ca ^ arx[1]) << 4));
            int cb = ks * 2 + bcb;
#pragma unroll
            for (int nfp = 0; nfp < 4; nfp++) {
                uint32_t bb[4];
                ldsm4(bb, sB + boff[nfp] + ((cb ^ brx[nfp]) << 4));
                mma_f16(c[0][2 * nfp],     a[0], bb[0], bb[1]);
                mma_f16(c[1][2 * nfp],     a[1], bb[0], bb[1]);
                mma_f16(c[0][2 * nfp + 1], a[0], bb[2], bb[3]);
                mma_f16(c[1][2 * nfp + 1], a[1], bb[2], bb[3]);
            }
        }
        __syncthreads();
    }
    CP_WAIT(0);

    float* Pp = P + (size_t)blockIdx.y * pstride;
#pragma unroll
    for (int mf = 0; mf < 2; mf++) {
        int r0 = m0 + warp_m0 + mf * 16 + g;
#pragma unroll
        for (int nf = 0; nf < 8; nf++) {
            int col = warp_n0 + nf * 8 + t * 2;
            if (r0 < M)
                *(float2*)&Pp[(size_t)r0 * CC + col] = make_float2(c[mf][nf][0], c[mf][nf][1]);
            if (r0 + 8 < M)
                *(float2*)&Pp[(size_t)(r0 + 8) * CC + col] = make_float2(c[mf][nf][2], c[mf][nf][3]);
        }
    }
#undef ISSUE
}

// ---------------- combine split-K partials + BN column sums -------------------
template <int SP>
__global__ void k_comb(const float* __restrict__ P, int pstride, int M,
                       float* __restrict__ out, float* __restrict__ red) {
    int c = threadIdx.x;
    float s = 0.f, s2 = 0.f;
    for (int r = blockIdx.x; r < M; r += gridDim.x) {
        size_t o = (size_t)r * CC + c;
        float v = P[o];
        if (SP > 1) v += P[pstride + o];
        if (SP > 2) v += P[2 * (size_t)pstride + o];
        out[o] = v;
        s += v; s2 += v * v;
    }
    atomicAdd(&red[c], s);
    atomicAdd(&red[CC + c], s2);
}

__global__ void k_stats(const float* __restrict__ red, const float* __restrict__ g,
                        const float* __restrict__ be, float* __restrict__ sc,
                        float* __restrict__ sh, int M) {
    int c = threadIdx.x;
    float mu = red[c] / (float)M;
    float var = red[CC + c] / (float)M - mu * mu;
    float s = g[c] * rsqrtf(var + 1e-5f);
    sc[c] = s;
    sh[c] = be[c] - mu * s;
}

__global__ void k_bnelu(const float* __restrict__ X, const float* __restrict__ sc,
                        const float* __restrict__ sh, __half* __restrict__ Y, int n) {
    int i = blockIdx.x * blockDim.x + threadIdx.x;
    if (i >= n) return;
    int c = i & (CC - 1);
    float v = X[i] * sc[c] + sh[c];
    Y[i] = __float2half(v > 0.f ? v : expm1f(v));
}

__global__ void k_final(const float* __restrict__ A, const float* __restrict__ B,
                        const float* __restrict__ sc2, const float* __restrict__ sh2,
                        const float* __restrict__ scS, const float* __restrict__ shS,
                        float* __restrict__ out, int n) {
    int i = blockIdx.x * blockDim.x + threadIdx.x;
    if (i >= n) return;
    int c = i & (CC - 1);
    float v = A[i] * sc2[c] + sh2[c] + B[i] * scS[c] + shS[c];
    out[i] = v > 0.f ? v : expm1f(v);
}

// ---------------- launch ----------------------------------------------------
extern "C" void kernel_launch(void* const* d_in, const int* in_sizes, int n_in,
                              void* d_out, int out_size) {
    const float* x    = (const float*)d_in[0];
    const int*   ei   = (const int*)d_in[1];
    const float* attr = (const float*)d_in[2];
    const float* W1   = (const float*)d_in[3];
    const float* Wr1  = (const float*)d_in[4];
    const float* g1   = (const float*)d_in[6];
    const float* be1  = (const float*)d_in[7];
    const float* W2   = (const float*)d_in[8];
    const float* Wr2  = (const float*)d_in[9];
    const float* g2   = (const float*)d_in[11];
    const float* be2  = (const float*)d_in[12];
    const float* Wsc  = (const float*)d_in[13];
    const float* Wrsc = (const float*)d_in[14];
    const float* gsc  = (const float*)d_in[16];
    const float* besc = (const float*)d_in[17];
    // bias inputs b1/b2/bsc dropped: constant column shifts cancel in train-mode BN

    int E = in_sizes[1] / 2;
    int M = in_sizes[0] / CI1;
    const int* src = ei;
    const int* dst = ei + E;

    __half *acc, *wt1, *wt2, *wts, *sinb, *h1e;
    float *part, *out1, *out2, *outs, *red, *scale, *shift;
    int *degcnt;
    cudaGetSymbolAddress((void**)&acc,    g_acc);
    cudaGetSymbolAddress((void**)&wt1,    g_wt1);
    cudaGetSymbolAddress((void**)&wt2,    g_wt2);
    cudaGetSymbolAddress((void**)&wts,    g_wts);
    cudaGetSymbolAddress((void**)&sinb,   g_sin);
    cudaGetSymbolAddress((void**)&h1e,    g_h1e);
    cudaGetSymbolAddress((void**)&part,   g_part);
    cudaGetSymbolAddress((void**)&out1,   g_out1);
    cudaGetSymbolAddress((void**)&out2,   g_out2);
    cudaGetSymbolAddress((void**)&outs,   g_outs);
    cudaGetSymbolAddress((void**)&red,    g_red);
    cudaGetSymbolAddress((void**)&scale,  g_scale);
    cudaGetSymbolAddress((void**)&shift,  g_shift);
    cudaGetSymbolAddress((void**)&degcnt, g_degcnt);

    cudaFuncSetAttribute((const void*)k_agg<CC, 0, __half>,
                         cudaFuncAttributeMaxDynamicSharedMemorySize, KT * CC * 4);
    int dsm = NSTAGE * STG_BYTES;   // 96KB
    cudaFuncSetAttribute(k_mgemm, cudaFuncAttributeMaxDynamicSharedMemorySize, dsm);

    int eb = (E + 255) / 256;
    int mtiles = (M + 127) / 128;
    int pstride = M * CC;

    // zero accumulators via memset nodes (not kernel launches)
    cudaMemsetAsync(degcnt, 0, M * sizeof(int));
    cudaMemsetAsync(red, 0, 6 * CC * sizeof(float));

    // CSR build (basis computed in k_fill, stored CSR-ordered)
    k_pre<<<eb, 256>>>(dst, E);                                       // launch 0
    k_scan<<<1, 1024>>>(M);                                           // launch 1
    k_fill<<<eb, 256>>>(attr, src, dst, E);                           // launch 2

    // conv1 agg (+fused shortcut agg), all weight transposes, conv1 GEMM
    k_agg<CI1, 1, float><<<M, CI1, KT * CI1 * 4>>>(x, x, LD1);        // launch 3
    k_transp3<<<dim3(LD2 / 32, CC / 32, 3), dim3(32, 8)>>>(
        W1, Wr1, W2, Wr2, Wsc, Wrsc, wt1, wt2, wts);                  // launch 4
    k_mgemm<<<dim3(mtiles, 3), 256, dsm>>>(acc, wt1, LD1, M, part, pstride,
                                           (LD1 / BK) / 3);           // launch 5 (profiled)
    k_comb<3><<<256, CC>>>(part, pstride, M, out1, red);
    k_stats<<<1, CC>>>(red, g1, be1, scale, shift, M);
    k_bnelu<<<(M * CC + 255) / 256, 256>>>(out1, scale, shift, h1e, M * CC);

    // conv2 (splitK=3)
    k_agg<CC, 0, __half><<<M, CC, KT * CC * 4>>>(h1e, x, LD2);
    k_mgemm<<<dim3(mtiles, 3), 256, dsm>>>(acc, wt2, LD2, M, part, pstride,
                                           (LD2 / BK) / 3);
    k_comb<3><<<256, CC>>>(part, pstride, M, out2, red + 2 * CC);
    k_stats<<<1, CC>>>(red + 2 * CC, g2, be2, scale + CC, shift + CC, M);

    // shortcut: [mean_agg | x] @ [Wsc ; Wrsc]
    k_mgemm<<<dim3(mtiles, 1), 256, dsm>>>(sinb, wts, CC, M, part, pstride, CC / BK);
    k_comb<1><<<256, CC>>>(part, pstride, M, outs, red + 4 * CC);
    k_stats<<<1, CC>>>(red + 4 * CC, gsc, besc, scale + 2 * CC, shift + 2 * CC, M);

    // final elu(bn2(h) + bnsc(s))
    k_final<<<(M * CC + 255) / 256, 256>>>(out2, outs, scale + CC, shift + CC,
                                           scale + 2 * CC, shift + 2 * CC,
                                           (float*)d_out, M * CC);
}

// round 11
// speedup vs baseline: 1.1055x; 1.1055x over previous
#include <cuda_runtime.h>
#include <cuda_fp16.h>
#include <math.h>
#include <stdint.h>

#define NMAX 10000
#define EMAX 160000
#define KT   125
#define CI1  64
#define CC   128
#define LD1  (KT*CI1 + CI1)    // 8064
#define LD2  (KT*CC + CC)      // 16128

// ---------------- scratch (device globals: no allocations allowed) ----------
__device__ __align__(1024) __half g_acc[(size_t)NMAX * LD2];  // 322MB
__device__ __align__(1024) __half g_wt1[CC * LD1];
__device__ __align__(1024) __half g_wt2[CC * LD2];
__device__ __align__(1024) __half g_wts[CC * CC];
__device__ __align__(1024) __half g_sin[NMAX * CC];           // [s_agg | x]
__device__ __align__(1024) __half g_h1e[NMAX * CC];           // elu(bn1(conv1)) fp16
__device__ __align__(1024) float g_part[3 * (size_t)NMAX * CC];
__device__ __align__(1024) float g_out1[NMAX * CC];
__device__ __align__(1024) float g_out2[NMAX * CC];
__device__ __align__(1024) float g_outs[NMAX * CC];
__device__ __align__(16) float g_w8  [EMAX * 8];   // CSR-ordered basis weights
__device__ __align__(16) int   g_idx8[EMAX * 8];   // CSR-ordered kernel indices
__device__ int   g_srco[EMAX];
__device__ int   g_rowptr[NMAX + 1];
__device__ int   g_cursor[NMAX];
__device__ int   g_degcnt[NMAX];
__device__ float g_red  [6 * CC];
__device__ float g_scale[3 * CC];
__device__ float g_shift[3 * CC];

// ---------------- helpers ----------------------------------------------------
__device__ __forceinline__ uint32_t smem_u32(const void* p) {
    uint32_t a;
    asm("{ .reg .u64 t; cvta.to.shared.u64 t, %1; cvt.u32.u64 %0, t; }" : "=r"(a) : "l"(p));
    return a;
}
__device__ __forceinline__ void cp_async16(uint32_t dst, const void* src, int vsize) {
    asm volatile("cp.async.cg.shared.global [%0], [%1], 16, %2;"
                 :: "r"(dst), "l"(src), "r"(vsize) : "memory");
}
#define CP_COMMIT() asm volatile("cp.async.commit_group;" ::: "memory")
#define CP_WAIT(n)  asm volatile("cp.async.wait_group %0;" :: "n"(n) : "memory")

__device__ __forceinline__ void ldsm4(uint32_t* r, uint32_t addr) {
    asm volatile("ldmatrix.sync.aligned.m8n8.x4.shared.b16 {%0,%1,%2,%3}, [%4];"
                 : "=r"(r[0]), "=r"(r[1]), "=r"(r[2]), "=r"(r[3]) : "r"(addr));
}
__device__ __forceinline__ void mma_f16(float* c, const uint32_t* a, uint32_t b0, uint32_t b1) {
    asm volatile("mma.sync.aligned.m16n8k16.row.col.f32.f16.f16.f32 "
                 "{%0,%1,%2,%3}, {%4,%5,%6,%7}, {%8,%9}, {%0,%1,%2,%3};"
                 : "+f"(c[0]), "+f"(c[1]), "+f"(c[2]), "+f"(c[3])
                 : "r"(a[0]), "r"(a[1]), "r"(a[2]), "r"(a[3]), "r"(b0), "r"(b1));
}

// ---------------- CSR build --------------------------------------------------
__global__ void k_pre(const int* __restrict__ dst, int E) {
    int e = blockIdx.x * blockDim.x + threadIdx.x;
    if (e < E) atomicAdd(&g_degcnt[dst[e]], 1);
}

__global__ void k_scan(int n) {
    __shared__ int sh[1024];
    __shared__ int carry;
    int t = threadIdx.x;
    if (t == 0) carry = 0;
    __syncthreads();
    for (int base = 0; base < n; base += 1024) {
        int i = base + t;
        int v = (i < n) ? g_degcnt[i] : 0;
        sh[t] = v;
        __syncthreads();
        for (int off = 1; off < 1024; off <<= 1) {
            int tv = (t >= off) ? sh[t - off] : 0;
            __syncthreads();
            sh[t] += tv;
            __syncthreads();
        }
        if (i < n) {
            int ex = carry + sh[t] - v;
            g_rowptr[i] = ex;
            g_cursor[i] = ex;
        }
        __syncthreads();
        if (t == 0) carry += sh[1023];
        __syncthreads();
    }
    if (t == 0) g_rowptr[n] = carry;
}

__global__ void k_fill(const float* __restrict__ attr, const int* __restrict__ src,
                       const int* __restrict__ dst, int E) {
    int e = blockIdx.x * blockDim.x + threadIdx.x;
    if (e >= E) return;
    int pos = atomicAdd(&g_cursor[dst[e]], 1);
    g_srco[pos] = src[e];
    float v0 = attr[e * 3 + 0] * 4.f, v1 = attr[e * 3 + 1] * 4.f, v2 = attr[e * 3 + 2] * 4.f;
    float b0 = floorf(v0), b1 = floorf(v1), b2 = floorf(v2);
    float f0 = v0 - b0, f1 = v1 - b1, f2 = v2 - b2;
    int i0 = (int)b0, i1 = (int)b1, i2 = (int)b2;
#pragma unroll
    for (int m = 0; m < 8; m++) {
        int t0 = m & 1, t1 = (m >> 1) & 1, t2 = (m >> 2) & 1;
        float w = (t0 ? f0 : 1.f - f0) * (t1 ? f1 : 1.f - f1) * (t2 ? f2 : 1.f - f2);
        int c0 = min(max(i0 + t0, 0), 4);
        int c1 = min(max(i1 + t1, 0), 4);
        int c2 = min(max(i2 + t2, 0), 4);
        g_idx8[pos * 8 + m] = (c0 * 5 + c1) * 5 + c2;
        g_w8[pos * 8 + m] = w;
    }
}

// ---------------- aggregation: 64-wide channel slices, vector prefetch -------
// block = 64 threads, one node x one 64-channel slice; smem = 125*64*4 = 32000B
template <int CIT, int WITH_S, typename T>
__global__ __launch_bounds__(64)
void k_agg(const T* __restrict__ X, const float* __restrict__ Xroot, int ldacc) {
    extern __shared__ float acc[];
    int n = blockIdx.x;
    int soff = blockIdx.y * 64;
    int c = threadIdx.x;
    float4 z4 = make_float4(0.f, 0.f, 0.f, 0.f);
    for (int i = c; i < KT * 64 / 4; i += 64) ((float4*)acc)[i] = z4;
    int jb = g_rowptr[n], je = g_rowptr[n + 1];
    float invd = (je > jb) ? 1.f / (float)(je - jb) : 1.f;
    float ss = 0.f;
    __syncthreads();

    const int4*   ip = (const int4*)g_idx8;
    const float4* wp = (const float4*)g_w8;
    float xv = 0.f;
    int4 ia = make_int4(0, 0, 0, 0), ib = ia;
    float4 wa = z4, wb = z4;
    if (jb < je) {
        xv = (float)X[(size_t)g_srco[jb] * CIT + soff + c];
        ia = ip[jb * 2]; ib = ip[jb * 2 + 1];
        wa = wp[jb * 2]; wb = wp[jb * 2 + 1];
    }
    for (int j = jb; j < je; j++) {
        float xc = xv;
        int4 ca = ia, cb = ib;
        float4 va = wa, vb = wb;
        if (j + 1 < je) {                      // prefetch next edge
            xv = (float)X[(size_t)g_srco[j + 1] * CIT + soff + c];
            ia = ip[(j + 1) * 2]; ib = ip[(j + 1) * 2 + 1];
            wa = wp[(j + 1) * 2]; wb = wp[(j + 1) * 2 + 1];
        }
        if (WITH_S) ss += xc;
        acc[ca.x * 64 + c] += va.x * xc;
        acc[ca.y * 64 + c] += va.y * xc;
        acc[ca.z * 64 + c] += va.z * xc;
        acc[ca.w * 64 + c] += va.w * xc;
        acc[cb.x * 64 + c] += vb.x * xc;
        acc[cb.y * 64 + c] += vb.y * xc;
        acc[cb.z * 64 + c] += vb.z * xc;
        acc[cb.w * 64 + c] += vb.w * xc;
    }
    __syncthreads();

    // vectorized writeout: float4 -> 4 halves (one 8B store)
    size_t base = (size_t)n * ldacc;
    for (int i = c; i < KT * 64 / 4; i += 64) {
        float4 v = ((const float4*)acc)[i];
        int bin = i >> 4;              // (i*4)/64
        int ch  = (i << 2) & 63;
        __half2 h0 = __floats2half2_rn(v.x * invd, v.y * invd);
        __half2 h1 = __floats2half2_rn(v.z * invd, v.w * invd);
        uint2 pk;
        pk.x = *(uint32_t*)&h0;
        pk.y = *(uint32_t*)&h1;
        *(uint2*)(g_acc + base + (size_t)bin * CIT + soff + ch) = pk;
    }
    g_acc[base + (size_t)KT * CIT + soff + c] = (__half)(float)X[(size_t)n * CIT + soff + c];
    if (WITH_S) {
        g_sin[n * CC + c]       = __float2half(ss * invd);
        g_sin[n * CC + CI1 + c] = __float2half(Xroot[n * CI1 + c]);
    }
}

// fused tiled transpose of all three weight sets -> wt[n][k] fp16
__global__ void k_transp3(const float* __restrict__ W1, const float* __restrict__ Wr1,
                          const float* __restrict__ W2, const float* __restrict__ Wr2,
                          const float* __restrict__ Ws, const float* __restrict__ Wrs,
                          __half* __restrict__ wt1, __half* __restrict__ wt2,
                          __half* __restrict__ wts) {
    __shared__ float tile[32][33];
    const float *W, *Wr; __half* out; int Kmain, Ktot;
    if (blockIdx.z == 0) { W = W1; Wr = Wr1; out = wt1; Kmain = KT * CI1; Ktot = LD1; }
    else if (blockIdx.z == 1) { W = W2; Wr = Wr2; out = wt2; Kmain = KT * CC; Ktot = LD2; }
    else { W = Ws; Wr = Wrs; out = wts; Kmain = CI1; Ktot = CC; }
    int kb = blockIdx.x * 32, nb = blockIdx.y * 32;
    if (kb >= Ktot) return;
    int tx = threadIdx.x, ty = threadIdx.y;
#pragma unroll
    for (int i = 0; i < 32; i += 8) {
        int k = kb + ty + i;
        const float* srcp = (k < Kmain) ? &W[(size_t)k * CC] : &Wr[(size_t)(k - Kmain) * CC];
        tile[ty + i][tx] = srcp[nb + tx];
    }
    __syncthreads();
#pragma unroll
    for (int i = 0; i < 32; i += 8) {
        int nn = nb + ty + i;
        out[(size_t)nn * Ktot + kb + tx] = __float2half(tile[tx][ty + i]);
    }
}

// ---------------- fp16 mma.sync GEMM with ldmatrix feed -----------------------
#define BK 64
#define NSTAGE 3
#define STG_BYTES 32768
#define TILE_BYTES 16384

__global__ __launch_bounds__(256, 2)
void k_mgemm(const __half* __restrict__ A, const __half* __restrict__ B, int ld,
             int M, float* __restrict__ P, int pstride, int chunks) {
    extern __shared__ char sm[];
    int tid = threadIdx.x, lane = tid & 31, wid = tid >> 5;
    int m0 = blockIdx.x * 128;
    int kb0 = blockIdx.y * chunks * BK;

    int pr_r = tid >> 1;
    int pr_h = (tid & 1) * 4;
    int grow = m0 + pr_r;
    int vA = (grow < M) ? 16 : 0;
    const __half* Abase = A + (size_t)grow * ld + kb0;
    const __half* Bbase = B + (size_t)pr_r * ld + kb0;

    const int warp_m0 = (wid & 3) * 32;
    const int warp_n0 = (wid >> 2) * 64;
    int g = lane >> 2, t = lane & 3;

    uint32_t aoff[2]; int arx[2];
#pragma unroll
    for (int mf = 0; mf < 2; mf++) {
        int r = warp_m0 + mf * 16 + (lane & 15);
        aoff[mf] = r * 128; arx[mf] = r & 7;
    }
    int acb = lane >> 4;
    int grp = lane >> 3;
    int nf_half = grp >> 1, bcb = grp & 1;
    uint32_t boff[4]; int brx[4];
#pragma unroll
    for (int nfp = 0; nfp < 4; nfp++) {
        int r = warp_n0 + (nfp * 2 + nf_half) * 8 + (lane & 7);
        boff[nfp] = r * 128; brx[nfp] = r & 7;
    }

    float c[2][8][4];
#pragma unroll
    for (int i = 0; i < 2; i++)
#pragma unroll
        for (int j = 0; j < 8; j++)
#pragma unroll
            for (int q = 0; q < 4; q++) c[i][j][q] = 0.f;

    uint32_t smb = smem_u32(sm);

#define ISSUE(IT) do { \
    int _it = (IT); \
    if (_it < chunks) { \
        int _s = _it % NSTAGE; \
        uint32_t _dA = smb + _s * STG_BYTES + pr_r * 128; \
        uint32_t _dB = _dA + TILE_BYTES; \
        const __half* _sa = Abase + _it * BK; \
        const __half* _sb = Bbase + _it * BK; \
        _Pragma("unroll") \
        for (int _j = 0; _j < 4; _j++) { \
            int _c = pr_h + _j; \
            int _sc = _c ^ (pr_r & 7); \
            cp_async16(_dA + _sc * 16, _sa + _c * 8, vA); \
            cp_async16(_dB + _sc * 16, _sb + _c * 8, 16); \
        } \
    } \
    CP_COMMIT(); \
} while (0)

    ISSUE(0); ISSUE(1);

    for (int it = 0; it < chunks; it++) {
        CP_WAIT(1);
        __syncthreads();
        ISSUE(it + 2);
        uint32_t sA = smb + (it % NSTAGE) * STG_BYTES;
        uint32_t sB = sA + TILE_BYTES;
#pragma unroll
        for (int ks = 0; ks < 4; ks++) {
            int ca = ks * 2 + acb;
            uint32_t a[2][4];
            ldsm4(a[0], sA + aoff[0] + ((ca ^ arx[0]) << 4));
            ldsm4(a[1], sA + aoff[1] + ((ca ^ arx[1]) << 4));
            int cb = ks * 2 + bcb;
#pragma unroll
            for (int nfp = 0; nfp < 4; nfp++) {
                uint32_t bb[4];
                ldsm4(bb, sB + boff[nfp] + ((cb ^ brx[nfp]) << 4));
                mma_f16(c[0][2 * nfp],     a[0], bb[0], bb[1]);
                mma_f16(c[1][2 * nfp],     a[1], bb[0], bb[1]);
                mma_f16(c[0][2 * nfp + 1], a[0], bb[2], bb[3]);
                mma_f16(c[1][2 * nfp + 1], a[1], bb[2], bb[3]);
            }
        }
        __syncthreads();
    }
    CP_WAIT(0);

    float* Pp = P + (size_t)blockIdx.y * pstride;
#pragma unroll
    for (int mf = 0; mf < 2; mf++) {
        int r0 = m0 + warp_m0 + mf * 16 + g;
#pragma unroll
        for (int nf = 0; nf < 8; nf++) {
            int col = warp_n0 + nf * 8 + t * 2;
            if (r0 < M)
                *(float2*)&Pp[(size_t)r0 * CC + col] = make_float2(c[mf][nf][0], c[mf][nf][1]);
            if (r0 + 8 < M)
                *(float2*)&Pp[(size_t)(r0 + 8) * CC + col] = make_float2(c[mf][nf][2], c[mf][nf][3]);
        }
    }
#undef ISSUE
}

// ---------------- combine split-K partials + BN column sums -------------------
template <int SP>
__global__ void k_comb(const float* __restrict__ P, int pstride, int M,
                       float* __restrict__ out, float* __restrict__ red) {
    int c = threadIdx.x;
    float s = 0.f, s2 = 0.f;
    for (int r = blockIdx.x; r < M; r += gridDim.x) {
        size_t o = (size_t)r * CC + c;
        float v = P[o];
        if (SP > 1) v += P[pstride + o];
        if (SP > 2) v += P[2 * (size_t)pstride + o];
        out[o] = v;
        s += v; s2 += v * v;
    }
    atomicAdd(&red[c], s);
    atomicAdd(&red[CC + c], s2);
}

__global__ void k_stats(const float* __restrict__ red, const float* __restrict__ g,
                        const float* __restrict__ be, float* __restrict__ sc,
                        float* __restrict__ sh, int M) {
    int c = threadIdx.x;
    float mu = red[c] / (float)M;
    float var = red[CC + c] / (float)M - mu * mu;
    float s = g[c] * rsqrtf(var + 1e-5f);
    sc[c] = s;
    sh[c] = be[c] - mu * s;
}

__global__ void k_bnelu(const float* __restrict__ X, const float* __restrict__ sc,
                        const float* __restrict__ sh, __half* __restrict__ Y, int n) {
    int i = blockIdx.x * blockDim.x + threadIdx.x;
    if (i >= n) return;
    int c = i & (CC - 1);
    float v = X[i] * sc[c] + sh[c];
    Y[i] = __float2half(v > 0.f ? v : expm1f(v));
}

__global__ void k_final(const float* __restrict__ A, const float* __restrict__ B,
                        const float* __restrict__ sc2, const float* __restrict__ sh2,
                        const float* __restrict__ scS, const float* __restrict__ shS,
                        float* __restrict__ out, int n) {
    int i = blockIdx.x * blockDim.x + threadIdx.x;
    if (i >= n) return;
    int c = i & (CC - 1);
    float v = A[i] * sc2[c] + sh2[c] + B[i] * scS[c] + shS[c];
    out[i] = v > 0.f ? v : expm1f(v);
}

// ---------------- launch ----------------------------------------------------
extern "C" void kernel_launch(void* const* d_in, const int* in_sizes, int n_in,
                              void* d_out, int out_size) {
    const float* x    = (const float*)d_in[0];
    const int*   ei   = (const int*)d_in[1];
    const float* attr = (const float*)d_in[2];
    const float* W1   = (const float*)d_in[3];
    const float* Wr1  = (const float*)d_in[4];
    const float* g1   = (const float*)d_in[6];
    const float* be1  = (const float*)d_in[7];
    const float* W2   = (const float*)d_in[8];
    const float* Wr2  = (const float*)d_in[9];
    const float* g2   = (const float*)d_in[11];
    const float* be2  = (const float*)d_in[12];
    const float* Wsc  = (const float*)d_in[13];
    const float* Wrsc = (const float*)d_in[14];
    const float* gsc  = (const float*)d_in[16];
    const float* besc = (const float*)d_in[17];

    int E = in_sizes[1] / 2;
    int M = in_sizes[0] / CI1;
    const int* src = ei;
    const int* dst = ei + E;

    __half *acc, *wt1, *wt2, *wts, *sinb, *h1e;
    float *part, *out1, *out2, *outs, *red, *scale, *shift;
    int *degcnt;
    cudaGetSymbolAddress((void**)&acc,    g_acc);
    cudaGetSymbolAddress((void**)&wt1,    g_wt1);
    cudaGetSymbolAddress((void**)&wt2,    g_wt2);
    cudaGetSymbolAddress((void**)&wts,    g_wts);
    cudaGetSymbolAddress((void**)&sinb,   g_sin);
    cudaGetSymbolAddress((void**)&h1e,    g_h1e);
    cudaGetSymbolAddress((void**)&part,   g_part);
    cudaGetSymbolAddress((void**)&out1,   g_out1);
    cudaGetSymbolAddress((void**)&out2,   g_out2);
    cudaGetSymbolAddress((void**)&outs,   g_outs);
    cudaGetSymbolAddress((void**)&red,    g_red);
    cudaGetSymbolAddress((void**)&scale,  g_scale);
    cudaGetSymbolAddress((void**)&shift,  g_shift);
    cudaGetSymbolAddress((void**)&degcnt, g_degcnt);

    int dsm = NSTAGE * STG_BYTES;   // 96KB
    cudaFuncSetAttribute(k_mgemm, cudaFuncAttributeMaxDynamicSharedMemorySize, dsm);

    int eb = (E + 255) / 256;
    int mtiles = (M + 127) / 128;
    int pstride = M * CC;
    int asm_bytes = KT * 64 * 4;    // 32000B, under 48KB default

    cudaMemsetAsync(degcnt, 0, M * sizeof(int));
    cudaMemsetAsync(red, 0, 6 * CC * sizeof(float));

    // CSR build
    k_pre<<<eb, 256>>>(dst, E);
    k_scan<<<1, 1024>>>(M);
    k_fill<<<eb, 256>>>(attr, src, dst, E);

    // conv1 agg (+fused shortcut agg), weight transposes, conv1 GEMM
    k_agg<CI1, 1, float><<<dim3(M, 1), 64, asm_bytes>>>(x, x, LD1);
    k_transp3<<<dim3(LD2 / 32, CC / 32, 3), dim3(32, 8)>>>(
        W1, Wr1, W2, Wr2, Wsc, Wrsc, wt1, wt2, wts);
    k_mgemm<<<dim3(mtiles, 3), 256, dsm>>>(acc, wt1, LD1, M, part, pstride,
                                           (LD1 / BK) / 3);
    k_comb<3><<<256, CC>>>(part, pstride, M, out1, red);
    k_stats<<<1, CC>>>(red, g1, be1, scale, shift, M);
    k_bnelu<<<(M * CC + 255) / 256, 256>>>(out1, scale, shift, h1e, M * CC);

    // conv2: channel-sliced aggregation (2 slices), GEMM splitK=3
    k_agg<CC, 0, __half><<<dim3(M, 2), 64, asm_bytes>>>(h1e, x, LD2);
    k_mgemm<<<dim3(mtiles, 3), 256, dsm>>>(acc, wt2, LD2, M, part, pstride,
                                           (LD2 / BK) / 3);
    k_comb<3><<<256, CC>>>(part, pstride, M, out2, red + 2 * CC);
    k_stats<<<1, CC>>>(red + 2 * CC, g2, be2, scale + CC, shift + CC, M);

    // shortcut: [mean_agg | x] @ [Wsc ; Wrsc]
    k_mgemm<<<dim3(mtiles, 1), 256, dsm>>>(sinb, wts, CC, M, part, pstride, CC / BK);
    k_comb<1><<<256, CC>>>(part, pstride, M, outs, red + 4 * CC);
    k_stats<<<1, CC>>>(red + 4 * CC, gsc, besc, scale + 2 * CC, shift + 2 * CC, M);

    // final elu(bn2(h) + bnsc(s))
    k_final<<<(M * CC + 255) / 256, 256>>>(out2, outs, scale + CC, shift + CC,
                                           scale + 2 * CC, shift + 2 * CC,
                                           (float*)d_out, M * CC);
}

// round 12
// speedup vs baseline: 1.2047x; 1.0898x over previous
#include <cuda_runtime.h>
#include <cuda_fp16.h>
#include <math.h>
#include <stdint.h>

#define NMAX 10000
#define EMAX 160000
#define KT   125
#define CI1  64
#define CC   128
#define LD1  (KT*CI1 + CI1)    // 8064
#define LD2  (KT*CC + CC)      // 16128

// ---------------- scratch (device globals: no allocations allowed) ----------
__device__ __align__(1024) __half g_acc[(size_t)NMAX * LD2];  // 322MB
__device__ __align__(1024) __half g_wt1[CC * LD1];
__device__ __align__(1024) __half g_wt2[CC * LD2];
__device__ __align__(1024) __half g_wts[CC * CC];
__device__ __align__(1024) __half g_sin[NMAX * CC];           // [s_agg | x]
__device__ __align__(1024) __half g_h1e[NMAX * CC];           // elu(bn1(conv1)) fp16
__device__ __align__(1024) float g_part[3 * (size_t)NMAX * CC];
__device__ __align__(1024) float g_out1[NMAX * CC];
__device__ __align__(1024) float g_out2[NMAX * CC];
__device__ __align__(1024) float g_outs[NMAX * CC];
__device__ __align__(16) float g_w8  [EMAX * 8];   // CSR-ordered basis weights
__device__ __align__(16) int   g_idx8[EMAX * 8];   // CSR-ordered kernel indices
__device__ int   g_srco[EMAX];
__device__ int   g_rowptr[NMAX + 1];
__device__ int   g_cursor[NMAX];
__device__ int   g_degcnt[NMAX];
__device__ float g_red  [6 * CC];
__device__ float g_scale[3 * CC];
__device__ float g_shift[3 * CC];

// ---------------- helpers ----------------------------------------------------
__device__ __forceinline__ uint32_t smem_u32(const void* p) {
    uint32_t a;
    asm("{ .reg .u64 t; cvta.to.shared.u64 t, %1; cvt.u32.u64 %0, t; }" : "=r"(a) : "l"(p));
    return a;
}
__device__ __forceinline__ void cp_async16(uint32_t dst, const void* src, int vsize) {
    asm volatile("cp.async.cg.shared.global [%0], [%1], 16, %2;"
                 :: "r"(dst), "l"(src), "r"(vsize) : "memory");
}
#define CP_COMMIT() asm volatile("cp.async.commit_group;" ::: "memory")
#define CP_WAIT(n)  asm volatile("cp.async.wait_group %0;" :: "n"(n) : "memory")

__device__ __forceinline__ void ldsm4(uint32_t* r, uint32_t addr) {
    asm volatile("ldmatrix.sync.aligned.m8n8.x4.shared.b16 {%0,%1,%2,%3}, [%4];"
                 : "=r"(r[0]), "=r"(r[1]), "=r"(r[2]), "=r"(r[3]) : "r"(addr));
}
__device__ __forceinline__ void mma_f16(float* c, const uint32_t* a, uint32_t b0, uint32_t b1) {
    asm volatile("mma.sync.aligned.m16n8k16.row.col.f32.f16.f16.f32 "
                 "{%0,%1,%2,%3}, {%4,%5,%6,%7}, {%8,%9}, {%0,%1,%2,%3};"
                 : "+f"(c[0]), "+f"(c[1]), "+f"(c[2]), "+f"(c[3])
                 : "r"(a[0]), "r"(a[1]), "r"(a[2]), "r"(a[3]), "r"(b0), "r"(b1));
}

// ---------------- CSR build --------------------------------------------------
__global__ void k_pre(const int* __restrict__ dst, int E) {
    int e = blockIdx.x * blockDim.x + threadIdx.x;
    if (e < E) atomicAdd(&g_degcnt[dst[e]], 1);
}

__global__ void k_scan(int n) {
    __shared__ int sh[1024];
    __shared__ int carry;
    int t = threadIdx.x;
    if (t == 0) carry = 0;
    __syncthreads();
    for (int base = 0; base < n; base += 1024) {
        int i = base + t;
        int v = (i < n) ? g_degcnt[i] : 0;
        sh[t] = v;
        __syncthreads();
        for (int off = 1; off < 1024; off <<= 1) {
            int tv = (t >= off) ? sh[t - off] : 0;
            __syncthreads();
            sh[t] += tv;
            __syncthreads();
        }
        if (i < n) {
            int ex = carry + sh[t] - v;
            g_rowptr[i] = ex;
            g_cursor[i] = ex;
        }
        __syncthreads();
        if (t == 0) carry += sh[1023];
        __syncthreads();
    }
    if (t == 0) g_rowptr[n] = carry;
}

__global__ void k_fill(const float* __restrict__ attr, const int* __restrict__ src,
                       const int* __restrict__ dst, int E) {
    int e = blockIdx.x * blockDim.x + threadIdx.x;
    if (e >= E) return;
    int pos = atomicAdd(&g_cursor[dst[e]], 1);
    g_srco[pos] = src[e];
    float v0 = attr[e * 3 + 0] * 4.f, v1 = attr[e * 3 + 1] * 4.f, v2 = attr[e * 3 + 2] * 4.f;
    float b0 = floorf(v0), b1 = floorf(v1), b2 = floorf(v2);
    float f0 = v0 - b0, f1 = v1 - b1, f2 = v2 - b2;
    int i0 = (int)b0, i1 = (int)b1, i2 = (int)b2;
#pragma unroll
    for (int m = 0; m < 8; m++) {
        int t0 = m & 1, t1 = (m >> 1) & 1, t2 = (m >> 2) & 1;
        float w = (t0 ? f0 : 1.f - f0) * (t1 ? f1 : 1.f - f1) * (t2 ? f2 : 1.f - f2);
        int c0 = min(max(i0 + t0, 0), 4);
        int c1 = min(max(i1 + t1, 0), 4);
        int c2 = min(max(i2 + t2, 0), 4);
        g_idx8[pos * 8 + m] = (c0 * 5 + c1) * 5 + c2;
        g_w8[pos * 8 + m] = w;
    }
}

// ---------------- aggregation: 256 thr = 4 edge-groups x 64 ch, smem atomics -
template <int CIT, int WITH_S, typename T>
__global__ __launch_bounds__(256)
void k_agg(const T* __restrict__ X, const float* __restrict__ Xroot, int ldacc) {
    extern __shared__ float acc[];      // KT*64 floats = 32000B
    __shared__ float sred[256];
    int n = blockIdx.x;
    int soff = blockIdx.y * 64;
    int tid = threadIdx.x;
    int c = tid & 63, grp = tid >> 6;
    float4 z4 = make_float4(0.f, 0.f, 0.f, 0.f);
    for (int i = tid; i < KT * 64 / 4; i += 256) ((float4*)acc)[i] = z4;
    int jb = g_rowptr[n], je = g_rowptr[n + 1];
    float invd = (je > jb) ? 1.f / (float)(je - jb) : 1.f;
    float ss = 0.f;
    __syncthreads();

    const int4*   ip = (const int4*)g_idx8;
    const float4* wp = (const float4*)g_w8;
    for (int j = jb + grp; j < je; j += 4) {
        float xc = (float)X[(size_t)g_srco[j] * CIT + soff + c];
        int4 ca = ip[j * 2], cb = ip[j * 2 + 1];
        float4 va = wp[j * 2], vb = wp[j * 2 + 1];
        if (WITH_S) ss += xc;
        atomicAdd(&acc[ca.x * 64 + c], va.x * xc);
        atomicAdd(&acc[ca.y * 64 + c], va.y * xc);
        atomicAdd(&acc[ca.z * 64 + c], va.z * xc);
        atomicAdd(&acc[ca.w * 64 + c], va.w * xc);
        atomicAdd(&acc[cb.x * 64 + c], vb.x * xc);
        atomicAdd(&acc[cb.y * 64 + c], vb.y * xc);
        atomicAdd(&acc[cb.z * 64 + c], vb.z * xc);
        atomicAdd(&acc[cb.w * 64 + c], vb.w * xc);
    }
    __syncthreads();

    // vectorized writeout: float4 -> 4 halves (one 8B store), 256 threads
    size_t base = (size_t)n * ldacc;
    for (int i = tid; i < KT * 64 / 4; i += 256) {
        float4 v = ((const float4*)acc)[i];
        int bin = i >> 4;
        int ch  = (i << 2) & 63;
        __half2 h0 = __floats2half2_rn(v.x * invd, v.y * invd);
        __half2 h1 = __floats2half2_rn(v.z * invd, v.w * invd);
        uint2 pk;
        pk.x = *(uint32_t*)&h0;
        pk.y = *(uint32_t*)&h1;
        *(uint2*)(g_acc + base + (size_t)bin * CIT + soff + ch) = pk;
    }
    if (tid < 64)
        g_acc[base + (size_t)KT * CIT + soff + tid] =
            (__half)(float)X[(size_t)n * CIT + soff + tid];
    if (WITH_S) {
        sred[tid] = ss;
        __syncthreads();
        if (tid < 64) {
            float s = sred[tid] + sred[tid + 64] + sred[tid + 128] + sred[tid + 192];
            g_sin[n * CC + tid]       = __float2half(s * invd);
            g_sin[n * CC + CI1 + tid] = __float2half(Xroot[n * CI1 + tid]);
        }
    }
}

// fused tiled transpose of all three weight sets -> wt[n][k] fp16
__global__ void k_transp3(const float* __restrict__ W1, const float* __restrict__ Wr1,
                          const float* __restrict__ W2, const float* __restrict__ Wr2,
                          const float* __restrict__ Ws, const float* __restrict__ Wrs,
                          __half* __restrict__ wt1, __half* __restrict__ wt2,
                          __half* __restrict__ wts) {
    __shared__ float tile[32][33];
    const float *W, *Wr; __half* out; int Kmain, Ktot;
    if (blockIdx.z == 0) { W = W1; Wr = Wr1; out = wt1; Kmain = KT * CI1; Ktot = LD1; }
    else if (blockIdx.z == 1) { W = W2; Wr = Wr2; out = wt2; Kmain = KT * CC; Ktot = LD2; }
    else { W = Ws; Wr = Wrs; out = wts; Kmain = CI1; Ktot = CC; }
    int kb = blockIdx.x * 32, nb = blockIdx.y * 32;
    if (kb >= Ktot) return;
    int tx = threadIdx.x, ty = threadIdx.y;
#pragma unroll
    for (int i = 0; i < 32; i += 8) {
        int k = kb + ty + i;
        const float* srcp = (k < Kmain) ? &W[(size_t)k * CC] : &Wr[(size_t)(k - Kmain) * CC];
        tile[ty + i][tx] = srcp[nb + tx];
    }
    __syncthreads();
#pragma unroll
    for (int i = 0; i < 32; i += 8) {
        int nn = nb + ty + i;
        out[(size_t)nn * Ktot + kb + tx] = __float2half(tile[tx][ty + i]);
    }
}

// ---------------- fp16 mma.sync GEMM with ldmatrix feed -----------------------
#define BK 64
#define NSTAGE 3
#define STG_BYTES 32768
#define TILE_BYTES 16384

__global__ __launch_bounds__(256, 2)
void k_mgemm(const __half* __restrict__ A, const __half* __restrict__ B, int ld,
             int M, float* __restrict__ P, int pstride, int chunks) {
    extern __shared__ char sm[];
    int tid = threadIdx.x, lane = tid & 31, wid = tid >> 5;
    int m0 = blockIdx.x * 128;
    int kb0 = blockIdx.y * chunks * BK;

    int pr_r = tid >> 1;
    int pr_h = (tid & 1) * 4;
    int grow = m0 + pr_r;
    int vA = (grow < M) ? 16 : 0;
    const __half* Abase = A + (size_t)grow * ld + kb0;
    const __half* Bbase = B + (size_t)pr_r * ld + kb0;

    const int warp_m0 = (wid & 3) * 32;
    const int warp_n0 = (wid >> 2) * 64;
    int g = lane >> 2, t = lane & 3;

    uint32_t aoff[2]; int arx[2];
#pragma unroll
    for (int mf = 0; mf < 2; mf++) {
        int r = warp_m0 + mf * 16 + (lane & 15);
        aoff[mf] = r * 128; arx[mf] = r & 7;
    }
    int acb = lane >> 4;
    int grp = lane >> 3;
    int nf_half = grp >> 1, bcb = grp & 1;
    uint32_t boff[4]; int brx[4];
#pragma unroll
    for (int nfp = 0; nfp < 4; nfp++) {
        int r = warp_n0 + (nfp * 2 + nf_half) * 8 + (lane & 7);
        boff[nfp] = r * 128; brx[nfp] = r & 7;
    }

    float c[2][8][4];
#pragma unroll
    for (int i = 0; i < 2; i++)
#pragma unroll
        for (int j = 0; j < 8; j++)
#pragma unroll
            for (int q = 0; q < 4; q++) c[i][j][q] = 0.f;

    uint32_t smb = smem_u32(sm);

#define ISSUE(IT) do { \
    int _it = (IT); \
    if (_it < chunks) { \
        int _s = _it % NSTAGE; \
        uint32_t _dA = smb + _s * STG_BYTES + pr_r * 128; \
        uint32_t _dB = _dA + TILE_BYTES; \
        const __half* _sa = Abase + _it * BK; \
        const __half* _sb = Bbase + _it * BK; \
        _Pragma("unroll") \
        for (int _j = 0; _j < 4; _j++) { \
            int _c = pr_h + _j; \
            int _sc = _c ^ (pr_r & 7); \
            cp_async16(_dA + _sc * 16, _sa + _c * 8, vA); \
            cp_async16(_dB + _sc * 16, _sb + _c * 8, 16); \
        } \
    } \
    CP_COMMIT(); \
} while (0)

    ISSUE(0); ISSUE(1);

    for (int it = 0; it < chunks; it++) {
        CP_WAIT(1);
        __syncthreads();
        ISSUE(it + 2);
        uint32_t sA = smb + (it % NSTAGE) * STG_BYTES;
        uint32_t sB = sA + TILE_BYTES;
#pragma unroll
        for (int ks = 0; ks < 4; ks++) {
            int ca = ks * 2 + acb;
            uint32_t a[2][4];
            ldsm4(a[0], sA + aoff[0] + ((ca ^ arx[0]) << 4));
            ldsm4(a[1], sA + aoff[1] + ((ca ^ arx[1]) << 4));
            int cb = ks * 2 + bcb;
#pragma unroll
            for (int nfp = 0; nfp < 4; nfp++) {
                uint32_t bb[4];
                ldsm4(bb, sB + boff[nfp] + ((cb ^ brx[nfp]) << 4));
                mma_f16(c[0][2 * nfp],     a[0], bb[0], bb[1]);
                mma_f16(c[1][2 * nfp],     a[1], bb[0], bb[1]);
                mma_f16(c[0][2 * nfp + 1], a[0], bb[2], bb[3]);
                mma_f16(c[1][2 * nfp + 1], a[1], bb[2], bb[3]);
            }
        }
        __syncthreads();
    }
    CP_WAIT(0);

    float* Pp = P + (size_t)blockIdx.y * pstride;
#pragma unroll
    for (int mf = 0; mf < 2; mf++) {
        int r0 = m0 + warp_m0 + mf * 16 + g;
#pragma unroll
        for (int nf = 0; nf < 8; nf++) {
            int col = warp_n0 + nf * 8 + t * 2;
            if (r0 < M)
                *(float2*)&Pp[(size_t)r0 * CC + col] = make_float2(c[mf][nf][0], c[mf][nf][1]);
            if (r0 + 8 < M)
                *(float2*)&Pp[(size_t)(r0 + 8) * CC + col] = make_float2(c[mf][nf][2], c[mf][nf][3]);
        }
    }
#undef ISSUE
}

// ---------------- combine split-K partials + BN column sums -------------------
template <int SP>
__global__ void k_comb(const float* __restrict__ P, int pstride, int M,
                       float* __restrict__ out, float* __restrict__ red) {
    int c = threadIdx.x;
    float s = 0.f, s2 = 0.f;
    for (int r = blockIdx.x; r < M; r += gridDim.x) {
        size_t o = (size_t)r * CC + c;
        float v = P[o];
        if (SP > 1) v += P[pstride + o];
        if (SP > 2) v += P[2 * (size_t)pstride + o];
        out[o] = v;
        s += v; s2 += v * v;
    }
    atomicAdd(&red[c], s);
    atomicAdd(&red[CC + c], s2);
}

__global__ void k_stats(const float* __restrict__ red, const float* __restrict__ g,
                        const float* __restrict__ be, float* __restrict__ sc,
                        float* __restrict__ sh, int M) {
    int c = threadIdx.x;
    float mu = red[c] / (float)M;
    float var = red[CC + c] / (float)M - mu * mu;
    float s = g[c] * rsqrtf(var + 1e-5f);
    sc[c] = s;
    sh[c] = be[c] - mu * s;
}

__global__ void k_bnelu(const float* __restrict__ X, const float* __restrict__ sc,
                        const float* __restrict__ sh, __half* __restrict__ Y, int n) {
    int i = blockIdx.x * blockDim.x + threadIdx.x;
    if (i >= n) return;
    int c = i & (CC - 1);
    float v = X[i] * sc[c] + sh[c];
    Y[i] = __float2half(v > 0.f ? v : expm1f(v));
}

__global__ void k_final(const float* __restrict__ A, const float* __restrict__ B,
                        const float* __restrict__ sc2, const float* __restrict__ sh2,
                        const float* __restrict__ scS, const float* __restrict__ shS,
                        float* __restrict__ out, int n) {
    int i = blockIdx.x * blockDim.x + threadIdx.x;
    if (i >= n) return;
    int c = i & (CC - 1);
    float v = A[i] * sc2[c] + sh2[c] + B[i] * scS[c] + shS[c];
    out[i] = v > 0.f ? v : expm1f(v);
}

// ---------------- launch ----------------------------------------------------
extern "C" void kernel_launch(void* const* d_in, const int* in_sizes, int n_in,
                              void* d_out, int out_size) {
    const float* x    = (const float*)d_in[0];
    const int*   ei   = (const int*)d_in[1];
    const float* attr = (const float*)d_in[2];
    const float* W1   = (const float*)d_in[3];
    const float* Wr1  = (const float*)d_in[4];
    const float* g1   = (const float*)d_in[6];
    const float* be1  = (const float*)d_in[7];
    const float* W2   = (const float*)d_in[8];
    const float* Wr2  = (const float*)d_in[9];
    const float* g2   = (const float*)d_in[11];
    const float* be2  = (const float*)d_in[12];
    const float* Wsc  = (const float*)d_in[13];
    const float* Wrsc = (const float*)d_in[14];
    const float* gsc  = (const float*)d_in[16];
    const float* besc = (const float*)d_in[17];

    int E = in_sizes[1] / 2;
    int M = in_sizes[0] / CI1;
    const int* src = ei;
    const int* dst = ei + E;

    __half *acc, *wt1, *wt2, *wts, *sinb, *h1e;
    float *part, *out1, *out2, *outs, *red, *scale, *shift;
    int *degcnt;
    cudaGetSymbolAddress((void**)&acc,    g_acc);
    cudaGetSymbolAddress((void**)&wt1,    g_wt1);
    cudaGetSymbolAddress((void**)&wt2,    g_wt2);
    cudaGetSymbolAddress((void**)&wts,    g_wts);
    cudaGetSymbolAddress((void**)&sinb,   g_sin);
    cudaGetSymbolAddress((void**)&h1e,    g_h1e);
    cudaGetSymbolAddress((void**)&part,   g_part);
    cudaGetSymbolAddress((void**)&out1,   g_out1);
    cudaGetSymbolAddress((void**)&out2,   g_out2);
    cudaGetSymbolAddress((void**)&outs,   g_outs);
    cudaGetSymbolAddress((void**)&red,    g_red);
    cudaGetSymbolAddress((void**)&scale,  g_scale);
    cudaGetSymbolAddress((void**)&shift,  g_shift);
    cudaGetSymbolAddress((void**)&degcnt, g_degcnt);

    int dsm = NSTAGE * STG_BYTES;   // 96KB
    cudaFuncSetAttribute(k_mgemm, cudaFuncAttributeMaxDynamicSharedMemorySize, dsm);

    int eb = (E + 255) / 256;
    int mtiles = (M + 127) / 128;
    int pstride = M * CC;
    int asm_bytes = KT * 64 * 4;    // 32000B

    cudaMemsetAsync(degcnt, 0, M * sizeof(int));
    cudaMemsetAsync(red, 0, 6 * CC * sizeof(float));

    // CSR build
    k_pre<<<eb, 256>>>(dst, E);
    k_scan<<<1, 1024>>>(M);
    k_fill<<<eb, 256>>>(attr, src, dst, E);

    // conv1 agg (+fused shortcut agg), weight transposes, conv1 GEMM
    k_agg<CI1, 1, float><<<dim3(M, 1), 256, asm_bytes>>>(x, x, LD1);
    k_transp3<<<dim3(LD2 / 32, CC / 32, 3), dim3(32, 8)>>>(
        W1, Wr1, W2, Wr2, Wsc, Wrsc, wt1, wt2, wts);
    k_mgemm<<<dim3(mtiles, 3), 256, dsm>>>(acc, wt1, LD1, M, part, pstride,
                                           (LD1 / BK) / 3);
    k_comb<3><<<256, CC>>>(part, pstride, M, out1, red);
    k_stats<<<1, CC>>>(red, g1, be1, scale, shift, M);
    k_bnelu<<<(M * CC + 255) / 256, 256>>>(out1, scale, shift, h1e, M * CC);

    // conv2: channel-sliced aggregation (2 slices), GEMM splitK=3
    k_agg<CC, 0, __half><<<dim3(M, 2), 256, asm_bytes>>>(h1e, x, LD2);
    k_mgemm<<<dim3(mtiles, 3), 256, dsm>>>(acc, wt2, LD2, M, part, pstride,
                                           (LD2 / BK) / 3);
    k_comb<3><<<256, CC>>>(part, pstride, M, out2, red + 2 * CC);
    k_stats<<<1, CC>>>(red + 2 * CC, g2, be2, scale + CC, shift + CC, M);

    // shortcut: [mean_agg | x] @ [Wsc ; Wrsc]
    k_mgemm<<<dim3(mtiles, 1), 256, dsm>>>(sinb, wts, CC, M, part, pstride, CC / BK);
    k_comb<1><<<256, CC>>>(part, pstride, M, outs, red + 4 * CC);
    k_stats<<<1, CC>>>(red + 4 * CC, gsc, besc, scale + 2 * CC, shift + 2 * CC, M);

    // final elu(bn2(h) + bnsc(s))
    k_final<<<(M * CC + 255) / 256, 256>>>(out2, outs, scale + CC, shift + CC,
                                           scale + 2 * CC, shift + 2 * CC,
                                           (float*)d_out, M * CC);
}